// round 2
// baseline (speedup 1.0000x reference)
#include <cuda_runtime.h>
#include <math.h>

// ---------------------------------------------------------------------------
// Problem constants
// ---------------------------------------------------------------------------
static constexpr int B_    = 32;
static constexpr int C_    = 256;
static constexpr int WS_   = 7;
static constexpr int NH    = 8;
static constexpr int NW    = 64;            // windows per image (8x8)
static constexpr int NWIN  = B_ * NW;       // 2048
static constexpr int NTOK  = WS_ * WS_ + 1; // 50
static constexpr int MBIG  = NWIN * NTOK;   // 102400
static constexpr int HID   = 4 * C_;        // 1024

// ---------------------------------------------------------------------------
// Scratch: __device__ globals, referenced directly by kernels (no
// cudaGetSymbolAddress in kernel_launch). Buffers are reused across stages:
//   g_BIG : QKV (stage C) then H1 (stage D)          [400 MB]
//   g_LN  : layernorm out, then ATT, then OUTB       [100 MB]
//   g_X   : window tokens (residual for stage C)     [100 MB]
//   g_TMP : post-attn state (residual for stage D)   [100 MB]
// ---------------------------------------------------------------------------
__device__ float g_X   [(size_t)MBIG * C_];
__device__ float g_LN  [(size_t)MBIG * C_];
__device__ float g_TMP [(size_t)MBIG * C_];
__device__ float g_BIG [(size_t)MBIG * HID];   // max(3*C, HID) = 1024 per row

__device__ float g_cflat[(size_t)NWIN * C_];
__device__ float g_cln  [(size_t)NWIN * C_];
__device__ float g_cqkv [(size_t)NWIN * 3 * C_];
__device__ float g_catt [(size_t)NWIN * C_];
__device__ float g_c2   [(size_t)NWIN * C_];

// ---------------------------------------------------------------------------
// LayerNorm: one block (256 threads) per row of length 256
// ---------------------------------------------------------------------------
__global__ void ln_kernel(const float* __restrict__ X,
                          const float* __restrict__ gw,
                          const float* __restrict__ gb,
                          float* __restrict__ Y)
{
    int row = blockIdx.x;
    int c   = threadIdx.x;
    float v = X[(size_t)row * C_ + c];
    float s = v, s2 = v * v;
    #pragma unroll
    for (int o = 16; o > 0; o >>= 1) {
        s  += __shfl_xor_sync(0xffffffffu, s,  o);
        s2 += __shfl_xor_sync(0xffffffffu, s2, o);
    }
    __shared__ float ss[8], ss2[8];
    int wid = c >> 5, lid = c & 31;
    if (lid == 0) { ss[wid] = s; ss2[wid] = s2; }
    __syncthreads();
    float ts = 0.f, ts2 = 0.f;
    #pragma unroll
    for (int i = 0; i < 8; i++) { ts += ss[i]; ts2 += ss2[i]; }
    float mu  = ts * (1.0f / C_);
    float var = ts2 * (1.0f / C_) - mu * mu;
    float r   = rsqrtf(var + 1e-5f);
    Y[(size_t)row * C_ + c] = (v - mu) * r * gw[c] + gb[c];
}

// ---------------------------------------------------------------------------
// SGEMM: C[M,N] = A[M,K] @ W[N,K]^T  (+bias, +GELU, +residual)
// 64x64x16 tile, 256 threads, 4x4 register tile per thread.
// ---------------------------------------------------------------------------
template<int ACT, bool HAS_BIAS, bool HAS_RES>
__global__ void __launch_bounds__(256)
gemm_kernel(const float* __restrict__ A, const float* __restrict__ W,
            const float* __restrict__ bias, const float* __restrict__ res,
            float* __restrict__ Cout, int M, int N, int K)
{
    __shared__ float As[16][64];
    __shared__ float Ws[16][64];

    int bm  = blockIdx.y * 64;
    int bn  = blockIdx.x * 64;
    int tid = threadIdx.x;
    int tx  = tid & 15;
    int ty  = tid >> 4;

    int lrow = tid >> 2;
    int lk4  = (tid & 3) * 4;

    float acc[4][4];
    #pragma unroll
    for (int i = 0; i < 4; i++)
        #pragma unroll
        for (int j = 0; j < 4; j++) acc[i][j] = 0.f;

    const float* Aptr = A + (size_t)(bm + lrow) * K + lk4;
    const float* Wptr = W + (size_t)(bn + lrow) * K + lk4;

    for (int k0 = 0; k0 < K; k0 += 16) {
        float4 av = *reinterpret_cast<const float4*>(Aptr + k0);
        float4 wv = *reinterpret_cast<const float4*>(Wptr + k0);
        As[lk4 + 0][lrow] = av.x; As[lk4 + 1][lrow] = av.y;
        As[lk4 + 2][lrow] = av.z; As[lk4 + 3][lrow] = av.w;
        Ws[lk4 + 0][lrow] = wv.x; Ws[lk4 + 1][lrow] = wv.y;
        Ws[lk4 + 2][lrow] = wv.z; Ws[lk4 + 3][lrow] = wv.w;
        __syncthreads();
        #pragma unroll
        for (int k = 0; k < 16; k++) {
            float4 a4 = *reinterpret_cast<const float4*>(&As[k][ty * 4]);
            float4 b4 = *reinterpret_cast<const float4*>(&Ws[k][tx * 4]);
            float a[4] = {a4.x, a4.y, a4.z, a4.w};
            float b[4] = {b4.x, b4.y, b4.z, b4.w};
            #pragma unroll
            for (int i = 0; i < 4; i++)
                #pragma unroll
                for (int j = 0; j < 4; j++)
                    acc[i][j] = fmaf(a[i], b[j], acc[i][j]);
        }
        __syncthreads();
    }

    #pragma unroll
    for (int i = 0; i < 4; i++) {
        int row = bm + ty * 4 + i;
        #pragma unroll
        for (int j = 0; j < 4; j++) {
            int col = bn + tx * 4 + j;
            float v = acc[i][j];
            if (HAS_BIAS) v += bias[col];
            if (ACT == 1) v = 0.5f * v * (1.0f + erff(v * 0.70710678118654752f));
            if (HAS_RES)  v += res[(size_t)row * N + col];
            Cout[(size_t)row * N + col] = v;
        }
    }
}

// ---------------------------------------------------------------------------
// Attention: one block per (window, head). NT tokens, head dim 32.
// QKV row layout: [q(256) | k(256) | v(256)]; head h = cols h*32..h*32+31.
// ---------------------------------------------------------------------------
template<int NT, bool BIAS>
__global__ void __launch_bounds__(64)
attn_kernel(const float* __restrict__ QKV,
            const float* __restrict__ rel_pos,
            float* __restrict__ OUT)
{
    int bh = blockIdx.x;
    int w  = bh >> 3;
    int h  = bh & 7;

    __shared__ float qs[NT][32], ks[NT][32], vs[NT][32];
    __shared__ float sc[NT][NT + 3];

    int tid = threadIdx.x;
    const float* base = QKV + (size_t)w * NT * 768 + h * 32;
    for (int idx = tid; idx < NT * 32; idx += 64) {
        int n = idx >> 5, d = idx & 31;
        const float* r = base + (size_t)n * 768 + d;
        qs[n][d] = r[0];
        ks[n][d] = r[256];
        vs[n][d] = r[512];
    }
    __syncthreads();

    if (tid < NT) {
        int n = tid;
        float q[32];
        #pragma unroll
        for (int d = 0; d < 32; d++) q[d] = qs[n][d];

        const float scale = 0.17677669529663687f;  // 1/sqrt(32)
        float mx = -1e30f;
        for (int m = 0; m < NT; m++) {
            float s = 0.f;
            #pragma unroll
            for (int d = 0; d < 32; d++) s = fmaf(q[d], ks[m][d], s);
            s *= scale;
            if (BIAS) {
                if (n > 0 && m > 0) {
                    int p = n - 1, qq = m - 1;
                    int ridx = ((p / 7) - (qq / 7) + 6) * 13 + ((p % 7) - (qq % 7) + 6);
                    s += rel_pos[h * 225 + ridx];
                }
            }
            sc[n][m] = s;
            mx = fmaxf(mx, s);
        }
        float sum = 0.f;
        for (int m = 0; m < NT; m++) {
            float e = expf(sc[n][m] - mx);
            sc[n][m] = e;
            sum += e;
        }
        float inv = 1.0f / sum;
        float o[32];
        #pragma unroll
        for (int d = 0; d < 32; d++) o[d] = 0.f;
        for (int m = 0; m < NT; m++) {
            float p = sc[n][m];
            #pragma unroll
            for (int d = 0; d < 32; d++) o[d] = fmaf(p, vs[m][d], o[d]);
        }
        float* orow = OUT + (size_t)(w * NT + n) * C_ + h * 32;
        #pragma unroll
        for (int d = 0; d < 32; d++) orow[d] = o[d] * inv;
    }
}

// ---------------------------------------------------------------------------
// Data movement (these reference the device globals directly)
// ---------------------------------------------------------------------------
__global__ void k_gather_cls(const float* __restrict__ cls)
{
    int idx = blockIdx.x * blockDim.x + threadIdx.x;
    if (idx >= NWIN * C_) return;
    int c = idx & 255, row = idx >> 8;
    int b = row >> 6, n = row & 63;
    g_cflat[idx] = cls[((size_t)b * C_ + c) * 64 + n];
}

__global__ void k_buildX(const float* __restrict__ patch)
{
    int idx = blockIdx.x * blockDim.x + threadIdx.x;
    if (idx >= MBIG * C_) return;
    int c = idx & 255, row = idx >> 8;
    int t = row % NTOK, w = row / NTOK;
    if (t == 0) {
        g_X[idx] = g_c2[(size_t)w * C_ + c];
    } else {
        int b = w >> 6, wi = w & 63;
        int hk = wi >> 3, wkx = wi & 7;
        int k = t - 1, i = k / 7, j = k % 7;
        g_X[idx] = patch[(((size_t)b * C_ + c) * 56 + hk * 7 + i) * 56 + wkx * 7 + j];
    }
}

__global__ void k_scatter(const float* __restrict__ T, float* __restrict__ out)
{
    int idx = blockIdx.x * blockDim.x + threadIdx.x;
    if (idx >= MBIG * C_) return;
    int c = idx & 255, row = idx >> 8;
    int t = row % NTOK, w = row / NTOK;
    int b = w >> 6, wi = w & 63;
    int hk = wi >> 3, wkx = wi & 7;
    float v = T[idx];
    if (t == 0) {
        out[(((size_t)b * C_ + c) * 8 + hk) * 8 + wkx] = v;
    } else {
        int k = t - 1, i = k / 7, j = k % 7;
        out[(size_t)B_ * C_ * 64 +
            (((size_t)b * C_ + c) * 56 + hk * 7 + i) * 56 + wkx * 7 + j] = v;
    }
}

// Tiny helper kernels to fetch scratch base pointers on the device side is
// unnecessary: we get raw pointers at launch time through a device-side
// trampoline. Instead, we pass the globals via kernel parameters captured
// with the & operator on the symbols — which is invalid on host. So the
// GEMM/LN/attention kernels below are launched with explicit wrapper
// kernels that alias the globals.
// Simplest approach: wrap each global access in a small __device__ getter.
__device__ float* p_X()    { return g_X; }

// ---------------------------------------------------------------------------
// Stage wrapper kernels: since host code cannot take addresses of __device__
// globals without cudaGetSymbolAddress, we launch template kernels that take
// no scratch pointers and instead use a compile-time tag to select buffers.
// To keep things simple we define thin wrapper kernels for each stage.
// ---------------------------------------------------------------------------

// LN wrappers
__global__ void ln_cls(const float* __restrict__ gw, const float* __restrict__ gb)
{
    // row = blockIdx.x over NWIN
    int row = blockIdx.x, c = threadIdx.x;
    float v = g_cflat[(size_t)row * C_ + c];
    float s = v, s2 = v * v;
    #pragma unroll
    for (int o = 16; o > 0; o >>= 1) {
        s  += __shfl_xor_sync(0xffffffffu, s,  o);
        s2 += __shfl_xor_sync(0xffffffffu, s2, o);
    }
    __shared__ float ss[8], ss2[8];
    int wid = c >> 5, lid = c & 31;
    if (lid == 0) { ss[wid] = s; ss2[wid] = s2; }
    __syncthreads();
    float ts = 0.f, ts2 = 0.f;
    #pragma unroll
    for (int i = 0; i < 8; i++) { ts += ss[i]; ts2 += ss2[i]; }
    float mu  = ts * (1.0f / C_);
    float var = ts2 * (1.0f / C_) - mu * mu;
    float r   = rsqrtf(var + 1e-5f);
    g_cln[(size_t)row * C_ + c] = (v - mu) * r * gw[c] + gb[c];
}

// ---------------------------------------------------------------------------
// Host launcher. We DO use cudaGetSymbolAddress — but outside graph capture
// concerns we guard it with a one-time resolution into host statics. Symbol
// resolution itself is not a stream operation, but to be maximally safe we
// do it on every call (idempotent, cheap, no allocation).
// ---------------------------------------------------------------------------
extern "C" void kernel_launch(void* const* d_in, const int* in_sizes, int n_in,
                              void* d_out, int out_size)
{
    (void)in_sizes; (void)n_in; (void)out_size;
    const float* cls_tokens   = (const float*)d_in[0];
    const float* patch_tokens = (const float*)d_in[1];
    const float* n0w = (const float*)d_in[2];
    const float* n0b = (const float*)d_in[3];
    const float* n1w = (const float*)d_in[4];
    const float* n1b = (const float*)d_in[5];
    const float* n2w = (const float*)d_in[6];
    const float* n2b = (const float*)d_in[7];
    const float* qkv_w  = (const float*)d_in[8];
    const float* proj_w = (const float*)d_in[9];
    const float* proj_b = (const float*)d_in[10];
    const float* rel_pos= (const float*)d_in[11];
    const float* fc1_w  = (const float*)d_in[12];
    const float* fc1_b  = (const float*)d_in[13];
    const float* fc2_w  = (const float*)d_in[14];
    const float* fc2_b  = (const float*)d_in[15];
    float* out = (float*)d_out;

    // Resolve scratch pointers once (process-static; NOT a stream op, legal
    // before/outside capture; harness calls kernel_launch once uncaptured
    // for correctness first, so these are resolved by capture time).
    static float *X = nullptr, *LN = nullptr, *TMP = nullptr, *BIG = nullptr;
    static float *cf = nullptr, *cl = nullptr, *cq = nullptr, *ca = nullptr, *c2 = nullptr;
    if (!X) {
        cudaGetSymbolAddress((void**)&X,   g_X);
        cudaGetSymbolAddress((void**)&LN,  g_LN);
        cudaGetSymbolAddress((void**)&TMP, g_TMP);
        cudaGetSymbolAddress((void**)&BIG, g_BIG);
        cudaGetSymbolAddress((void**)&cf,  g_cflat);
        cudaGetSymbolAddress((void**)&cl,  g_cln);
        cudaGetSymbolAddress((void**)&cq,  g_cqkv);
        cudaGetSymbolAddress((void**)&ca,  g_catt);
        cudaGetSymbolAddress((void**)&c2,  g_c2);
    }

    const int TPB = 256;

    // ---- Stage A: cls MHA over 32 batches x 64 tokens ----
    k_gather_cls<<<(NWIN * C_ + TPB - 1) / TPB, TPB>>>(cls_tokens);
    ln_cls<<<NWIN, C_>>>(n0w, n0b);
    gemm_kernel<0, false, false><<<dim3(3 * C_ / 64, NWIN / 64), 256>>>(
        cl, qkv_w, nullptr, nullptr, cq, NWIN, 3 * C_, C_);
    attn_kernel<64, false><<<B_ * NH, 64>>>(cq, nullptr, ca);
    gemm_kernel<0, true, true><<<dim3(C_ / 64, NWIN / 64), 256>>>(
        ca, proj_w, proj_b, cf, c2, NWIN, C_, C_);

    // ---- Stage B: build X (102400 x 256) ----
    k_buildX<<<(MBIG * C_ + TPB - 1) / TPB, TPB>>>(patch_tokens);

    // ---- Stage C: windowed MHA + rel bias ----
    ln_kernel<<<MBIG, C_>>>(X, n1w, n1b, LN);
    gemm_kernel<0, false, false><<<dim3(3 * C_ / 64, MBIG / 64), 256>>>(
        LN, qkv_w, nullptr, nullptr, BIG, MBIG, 3 * C_, C_);     // BIG = QKV
    attn_kernel<50, true><<<NWIN * NH, 64>>>(BIG, rel_pos, LN);  // LN = ATT (LN dead)
    gemm_kernel<0, true, true><<<dim3(C_ / 64, MBIG / 64), 256>>>(
        LN, proj_w, proj_b, X, TMP, MBIG, C_, C_);

    // ---- Stage D: MLP ----
    ln_kernel<<<MBIG, C_>>>(TMP, n2w, n2b, LN);                  // LN reused
    gemm_kernel<1, true, false><<<dim3(HID / 64, MBIG / 64), 256>>>(
        LN, fc1_w, fc1_b, nullptr, BIG, MBIG, HID, C_);          // BIG = H1 (QKV dead)
    gemm_kernel<0, true, true><<<dim3(C_ / 64, MBIG / 64), 256>>>(
        BIG, fc2_w, fc2_b, TMP, X, MBIG, C_, HID);               // X = OUTB (X dead)

    // ---- Stage E: scatter ----
    k_scatter<<<(MBIG * C_ + TPB - 1) / TPB, TPB>>>(X, out);
}

// round 3
// speedup vs baseline: 2.0129x; 2.0129x over previous
#include <cuda_runtime.h>
#include <cuda_bf16.h>
#include <math.h>

// ---------------------------------------------------------------------------
// Problem constants
// ---------------------------------------------------------------------------
static constexpr int B_    = 32;
static constexpr int C_    = 256;
static constexpr int WS_   = 7;
static constexpr int NH    = 8;
static constexpr int NW    = 64;            // windows per image (8x8)
static constexpr int NWIN  = B_ * NW;       // 2048
static constexpr int NTOK  = WS_ * WS_ + 1; // 50
static constexpr int MBIG  = NWIN * NTOK;   // 102400
static constexpr int HID   = 4 * C_;        // 1024

// ---------------------------------------------------------------------------
// Scratch (device globals). Reused across stages:
//   g_BIG : QKV (stage C) then H1 (stage D)
//   g_LN  : LN out -> ATT -> (dead)
//   g_X   : window tokens (residual stage C) -> final out buffer
//   g_TMP : post-attn state (residual stage D)
// ---------------------------------------------------------------------------
__device__ float g_X   [(size_t)MBIG * C_];
__device__ float g_LN  [(size_t)MBIG * C_];
__device__ float g_TMP [(size_t)MBIG * C_];
__device__ float g_BIG [(size_t)MBIG * HID];

__device__ float g_cflat[(size_t)NWIN * C_];
__device__ float g_cln  [(size_t)NWIN * C_];
__device__ float g_cqkv [(size_t)NWIN * 3 * C_];
__device__ float g_catt [(size_t)NWIN * C_];
__device__ float g_c2   [(size_t)NWIN * C_];

// ---------------------------------------------------------------------------
// LayerNorm: one block (256 threads) per row of length 256
// ---------------------------------------------------------------------------
__global__ void ln_kernel(const float* __restrict__ X,
                          const float* __restrict__ gw,
                          const float* __restrict__ gb,
                          float* __restrict__ Y)
{
    int row = blockIdx.x;
    int c   = threadIdx.x;
    float v = X[(size_t)row * C_ + c];
    float s = v, s2 = v * v;
    #pragma unroll
    for (int o = 16; o > 0; o >>= 1) {
        s  += __shfl_xor_sync(0xffffffffu, s,  o);
        s2 += __shfl_xor_sync(0xffffffffu, s2, o);
    }
    __shared__ float ss[8], ss2[8];
    int wid = c >> 5, lid = c & 31;
    if (lid == 0) { ss[wid] = s; ss2[wid] = s2; }
    __syncthreads();
    float ts = 0.f, ts2 = 0.f;
    #pragma unroll
    for (int i = 0; i < 8; i++) { ts += ss[i]; ts2 += ss2[i]; }
    float mu  = ts * (1.0f / C_);
    float var = ts2 * (1.0f / C_) - mu * mu;
    float r   = rsqrtf(var + 1e-5f);
    Y[(size_t)row * C_ + c] = (v - mu) * r * gw[c] + gb[c];
}

// ---------------------------------------------------------------------------
// Split-bf16 tensor-core GEMM:  C[M,N] = A[M,K] @ W[N,K]^T (+bias,+GELU,+res)
// Each fp32 x = hi(bf16) + lo(bf16); C = Ah*Bh + Ah*Bl + Al*Bh  (f32 accum).
// CTA tile 128x64x32, 8 warps (4x2), warp tile 32x32, mma.m16n8k16.bf16.
// Requires M%128==0, N%64==0, K%32==0 (all shapes here satisfy this).
// ---------------------------------------------------------------------------
__device__ __forceinline__ void mma16816(float* c, const unsigned* a, const unsigned* b)
{
    asm volatile(
        "mma.sync.aligned.m16n8k16.row.col.f32.bf16.bf16.f32 "
        "{%0,%1,%2,%3},{%4,%5,%6,%7},{%8,%9},{%0,%1,%2,%3};"
        : "+f"(c[0]), "+f"(c[1]), "+f"(c[2]), "+f"(c[3])
        : "r"(a[0]), "r"(a[1]), "r"(a[2]), "r"(a[3]), "r"(b[0]), "r"(b[1]));
}

__device__ __forceinline__ void cvt4(float4 v, unsigned& h01, unsigned& h23,
                                     unsigned& l01, unsigned& l23)
{
    __nv_bfloat16 h0 = __float2bfloat16(v.x);
    __nv_bfloat16 h1 = __float2bfloat16(v.y);
    __nv_bfloat16 h2 = __float2bfloat16(v.z);
    __nv_bfloat16 h3 = __float2bfloat16(v.w);
    __nv_bfloat16 l0 = __float2bfloat16(v.x - __bfloat162float(h0));
    __nv_bfloat16 l1 = __float2bfloat16(v.y - __bfloat162float(h1));
    __nv_bfloat16 l2 = __float2bfloat16(v.z - __bfloat162float(h2));
    __nv_bfloat16 l3 = __float2bfloat16(v.w - __bfloat162float(h3));
    h01 = (unsigned)__bfloat16_as_ushort(h0) | ((unsigned)__bfloat16_as_ushort(h1) << 16);
    h23 = (unsigned)__bfloat16_as_ushort(h2) | ((unsigned)__bfloat16_as_ushort(h3) << 16);
    l01 = (unsigned)__bfloat16_as_ushort(l0) | ((unsigned)__bfloat16_as_ushort(l1) << 16);
    l23 = (unsigned)__bfloat16_as_ushort(l2) | ((unsigned)__bfloat16_as_ushort(l3) << 16);
}

template<int ACT, bool HAS_BIAS, bool HAS_RES>
__global__ void __launch_bounds__(256)
gemm_tc(const float* __restrict__ A, const float* __restrict__ W,
        const float* __restrict__ bias, const float* __restrict__ res,
        float* __restrict__ Cout, int M, int N, int K)
{
    constexpr int BM = 128, BN = 64, BK = 32, PAD = 40;
    __shared__ __align__(16) unsigned short Ah[BM * PAD], Al[BM * PAD];
    __shared__ __align__(16) unsigned short Bh[BN * PAD], Bl[BN * PAD];

    const int tid  = threadIdx.x;
    const int wrp  = tid >> 5;
    const int lane = tid & 31;
    const int g    = lane >> 2;     // groupID 0..7
    const int q4   = lane & 3;      // quad 0..3
    const int wm   = (wrp & 3) * 32;  // warp M offset in CTA tile
    const int wn   = (wrp >> 2) * 32; // warp N offset

    const int bm = blockIdx.y * BM;
    const int bn = blockIdx.x * BN;

    float acc[2][4][4];
    #pragma unroll
    for (int i = 0; i < 2; i++)
        #pragma unroll
        for (int j = 0; j < 4; j++)
            #pragma unroll
            for (int t = 0; t < 4; t++) acc[i][j][t] = 0.f;

    float4 aReg[4], bReg[2];
    const int KT = K / BK;

    // Global prefetch of k-tile kt into registers
    auto loadG = [&](int kt) {
        const float* Abase = A + (size_t)bm * K + kt * BK;
        #pragma unroll
        for (int i = 0; i < 4; i++) {
            int u = tid + i * 256, r = u >> 3, f = u & 7;
            aReg[i] = *reinterpret_cast<const float4*>(Abase + (size_t)r * K + f * 4);
        }
        const float* Wbase = W + (size_t)bn * K + kt * BK;
        #pragma unroll
        for (int i = 0; i < 2; i++) {
            int u = tid + i * 256, r = u >> 3, f = u & 7;
            bReg[i] = *reinterpret_cast<const float4*>(Wbase + (size_t)r * K + f * 4);
        }
    };
    // Convert + store staged regs into smem
    auto stS = [&]() {
        #pragma unroll
        for (int i = 0; i < 4; i++) {
            int u = tid + i * 256, r = u >> 3, f = u & 7;
            unsigned h01, h23, l01, l23;
            cvt4(aReg[i], h01, h23, l01, l23);
            *reinterpret_cast<uint2*>(&Ah[r * PAD + f * 4]) = make_uint2(h01, h23);
            *reinterpret_cast<uint2*>(&Al[r * PAD + f * 4]) = make_uint2(l01, l23);
        }
        #pragma unroll
        for (int i = 0; i < 2; i++) {
            int u = tid + i * 256, r = u >> 3, f = u & 7;
            unsigned h01, h23, l01, l23;
            cvt4(bReg[i], h01, h23, l01, l23);
            *reinterpret_cast<uint2*>(&Bh[r * PAD + f * 4]) = make_uint2(h01, h23);
            *reinterpret_cast<uint2*>(&Bl[r * PAD + f * 4]) = make_uint2(l01, l23);
        }
    };

    loadG(0);
    stS();
    __syncthreads();

    for (int kt = 0; kt < KT; kt++) {
        if (kt + 1 < KT) loadG(kt + 1);

        #pragma unroll
        for (int kk = 0; kk < 2; kk++) {
            const int k0 = kk * 16;
            unsigned a_h[2][4], a_l[2][4], b_h[4][2], b_l[4][2];
            #pragma unroll
            for (int mt = 0; mt < 2; mt++) {
                int r = wm + mt * 16 + g;
                int c = k0 + q4 * 2;
                a_h[mt][0] = *reinterpret_cast<unsigned*>(&Ah[r * PAD + c]);
                a_h[mt][1] = *reinterpret_cast<unsigned*>(&Ah[(r + 8) * PAD + c]);
                a_h[mt][2] = *reinterpret_cast<unsigned*>(&Ah[r * PAD + c + 8]);
                a_h[mt][3] = *reinterpret_cast<unsigned*>(&Ah[(r + 8) * PAD + c + 8]);
                a_l[mt][0] = *reinterpret_cast<unsigned*>(&Al[r * PAD + c]);
                a_l[mt][1] = *reinterpret_cast<unsigned*>(&Al[(r + 8) * PAD + c]);
                a_l[mt][2] = *reinterpret_cast<unsigned*>(&Al[r * PAD + c + 8]);
                a_l[mt][3] = *reinterpret_cast<unsigned*>(&Al[(r + 8) * PAD + c + 8]);
            }
            #pragma unroll
            for (int nt = 0; nt < 4; nt++) {
                int n = wn + nt * 8 + g;
                int c = k0 + q4 * 2;
                b_h[nt][0] = *reinterpret_cast<unsigned*>(&Bh[n * PAD + c]);
                b_h[nt][1] = *reinterpret_cast<unsigned*>(&Bh[n * PAD + c + 8]);
                b_l[nt][0] = *reinterpret_cast<unsigned*>(&Bl[n * PAD + c]);
                b_l[nt][1] = *reinterpret_cast<unsigned*>(&Bl[n * PAD + c + 8]);
            }
            #pragma unroll
            for (int mt = 0; mt < 2; mt++)
                #pragma unroll
                for (int nt = 0; nt < 4; nt++) {
                    mma16816(acc[mt][nt], a_h[mt], b_h[nt]);
                    mma16816(acc[mt][nt], a_h[mt], b_l[nt]);
                    mma16816(acc[mt][nt], a_l[mt], b_h[nt]);
                }
        }
        __syncthreads();
        if (kt + 1 < KT) { stS(); __syncthreads(); }
    }

    // Epilogue
    #pragma unroll
    for (int mt = 0; mt < 2; mt++) {
        #pragma unroll
        for (int nt = 0; nt < 4; nt++) {
            int row0 = bm + wm + mt * 16 + g;
            int col0 = bn + wn + nt * 8 + q4 * 2;
            #pragma unroll
            for (int t = 0; t < 4; t++) {
                int row = row0 + (t >> 1) * 8;
                int col = col0 + (t & 1);
                float v = acc[mt][nt][t];
                if (HAS_BIAS) v += bias[col];
                if (ACT == 1) v = 0.5f * v * (1.0f + erff(v * 0.70710678118654752f));
                if (HAS_RES)  v += res[(size_t)row * N + col];
                Cout[(size_t)row * N + col] = v;
            }
        }
    }
}

// ---------------------------------------------------------------------------
// Attention: one block per (window, head). NT tokens, head dim 32.
// QKV row layout: [q(256) | k(256) | v(256)]; head h = cols h*32..h*32+31.
// ---------------------------------------------------------------------------
template<int NT, bool BIAS>
__global__ void __launch_bounds__(64)
attn_kernel(const float* __restrict__ QKV,
            const float* __restrict__ rel_pos,
            float* __restrict__ OUT)
{
    int bh = blockIdx.x;
    int w  = bh >> 3;
    int h  = bh & 7;

    __shared__ float qs[NT][32], ks[NT][32], vs[NT][32];
    __shared__ float sc[NT][NT + 3];

    int tid = threadIdx.x;
    const float* base = QKV + (size_t)w * NT * 768 + h * 32;
    for (int idx = tid; idx < NT * 32; idx += 64) {
        int n = idx >> 5, d = idx & 31;
        const float* r = base + (size_t)n * 768 + d;
        qs[n][d] = r[0];
        ks[n][d] = r[256];
        vs[n][d] = r[512];
    }
    __syncthreads();

    if (tid < NT) {
        int n = tid;
        float q[32];
        #pragma unroll
        for (int d = 0; d < 32; d++) q[d] = qs[n][d];

        const float scale = 0.17677669529663687f;  // 1/sqrt(32)
        float mx = -1e30f;
        for (int m = 0; m < NT; m++) {
            float s = 0.f;
            #pragma unroll
            for (int d = 0; d < 32; d++) s = fmaf(q[d], ks[m][d], s);
            s *= scale;
            if (BIAS) {
                if (n > 0 && m > 0) {
                    int p = n - 1, qq = m - 1;
                    int ridx = ((p / 7) - (qq / 7) + 6) * 13 + ((p % 7) - (qq % 7) + 6);
                    s += rel_pos[h * 225 + ridx];
                }
            }
            sc[n][m] = s;
            mx = fmaxf(mx, s);
        }
        float sum = 0.f;
        for (int m = 0; m < NT; m++) {
            float e = expf(sc[n][m] - mx);
            sc[n][m] = e;
            sum += e;
        }
        float inv = 1.0f / sum;
        float o[32];
        #pragma unroll
        for (int d = 0; d < 32; d++) o[d] = 0.f;
        for (int m = 0; m < NT; m++) {
            float p = sc[n][m];
            #pragma unroll
            for (int d = 0; d < 32; d++) o[d] = fmaf(p, vs[m][d], o[d]);
        }
        float* orow = OUT + (size_t)(w * NT + n) * C_ + h * 32;
        #pragma unroll
        for (int d = 0; d < 32; d++) orow[d] = o[d] * inv;
    }
}

// ---------------------------------------------------------------------------
// Data movement
// ---------------------------------------------------------------------------
__global__ void k_gather_cls(const float* __restrict__ cls)
{
    int idx = blockIdx.x * blockDim.x + threadIdx.x;
    if (idx >= NWIN * C_) return;
    int c = idx & 255, row = idx >> 8;
    int b = row >> 6, n = row & 63;
    g_cflat[idx] = cls[((size_t)b * C_ + c) * 64 + n];
}

__global__ void k_buildX(const float* __restrict__ patch)
{
    int idx = blockIdx.x * blockDim.x + threadIdx.x;
    if (idx >= MBIG * C_) return;
    int c = idx & 255, row = idx >> 8;
    int t = row % NTOK, w = row / NTOK;
    if (t == 0) {
        g_X[idx] = g_c2[(size_t)w * C_ + c];
    } else {
        int b = w >> 6, wi = w & 63;
        int hk = wi >> 3, wkx = wi & 7;
        int k = t - 1, i = k / 7, j = k % 7;
        g_X[idx] = patch[(((size_t)b * C_ + c) * 56 + hk * 7 + i) * 56 + wkx * 7 + j];
    }
}

__global__ void k_scatter(const float* __restrict__ T, float* __restrict__ out)
{
    int idx = blockIdx.x * blockDim.x + threadIdx.x;
    if (idx >= MBIG * C_) return;
    int c = idx & 255, row = idx >> 8;
    int t = row % NTOK, w = row / NTOK;
    int b = w >> 6, wi = w & 63;
    int hk = wi >> 3, wkx = wi & 7;
    float v = T[idx];
    if (t == 0) {
        out[(((size_t)b * C_ + c) * 8 + hk) * 8 + wkx] = v;
    } else {
        int k = t - 1, i = k / 7, j = k % 7;
        out[(size_t)B_ * C_ * 64 +
            (((size_t)b * C_ + c) * 56 + hk * 7 + i) * 56 + wkx * 7 + j] = v;
    }
}

// ---------------------------------------------------------------------------
// Host launcher
// ---------------------------------------------------------------------------
extern "C" void kernel_launch(void* const* d_in, const int* in_sizes, int n_in,
                              void* d_out, int out_size)
{
    (void)in_sizes; (void)n_in; (void)out_size;
    const float* cls_tokens   = (const float*)d_in[0];
    const float* patch_tokens = (const float*)d_in[1];
    const float* n0w = (const float*)d_in[2];
    const float* n0b = (const float*)d_in[3];
    const float* n1w = (const float*)d_in[4];
    const float* n1b = (const float*)d_in[5];
    const float* n2w = (const float*)d_in[6];
    const float* n2b = (const float*)d_in[7];
    const float* qkv_w  = (const float*)d_in[8];
    const float* proj_w = (const float*)d_in[9];
    const float* proj_b = (const float*)d_in[10];
    const float* rel_pos= (const float*)d_in[11];
    const float* fc1_w  = (const float*)d_in[12];
    const float* fc1_b  = (const float*)d_in[13];
    const float* fc2_w  = (const float*)d_in[14];
    const float* fc2_b  = (const float*)d_in[15];
    float* out = (float*)d_out;

    static float *X = nullptr, *LN = nullptr, *TMP = nullptr, *BIG = nullptr;
    static float *cf = nullptr, *cl = nullptr, *cq = nullptr, *ca = nullptr, *c2 = nullptr;
    if (!X) {
        cudaGetSymbolAddress((void**)&X,   g_X);
        cudaGetSymbolAddress((void**)&LN,  g_LN);
        cudaGetSymbolAddress((void**)&TMP, g_TMP);
        cudaGetSymbolAddress((void**)&BIG, g_BIG);
        cudaGetSymbolAddress((void**)&cf,  g_cflat);
        cudaGetSymbolAddress((void**)&cl,  g_cln);
        cudaGetSymbolAddress((void**)&cq,  g_cqkv);
        cudaGetSymbolAddress((void**)&ca,  g_catt);
        cudaGetSymbolAddress((void**)&c2,  g_c2);
    }

    const int TPB = 256;

    // ---- Stage A: cls MHA over 32 batches x 64 tokens ----
    k_gather_cls<<<(NWIN * C_ + TPB - 1) / TPB, TPB>>>(cls_tokens);
    ln_kernel<<<NWIN, C_>>>(cf, n0w, n0b, cl);
    gemm_tc<0, false, false><<<dim3(3 * C_ / 64, NWIN / 128), 256>>>(
        cl, qkv_w, nullptr, nullptr, cq, NWIN, 3 * C_, C_);
    attn_kernel<64, false><<<B_ * NH, 64>>>(cq, nullptr, ca);
    gemm_tc<0, true, true><<<dim3(C_ / 64, NWIN / 128), 256>>>(
        ca, proj_w, proj_b, cf, c2, NWIN, C_, C_);

    // ---- Stage B: build X (102400 x 256) ----
    k_buildX<<<(MBIG * C_ + TPB - 1) / TPB, TPB>>>(patch_tokens);

    // ---- Stage C: windowed MHA + rel bias ----
    ln_kernel<<<MBIG, C_>>>(X, n1w, n1b, LN);
    gemm_tc<0, false, false><<<dim3(3 * C_ / 64, MBIG / 128), 256>>>(
        LN, qkv_w, nullptr, nullptr, BIG, MBIG, 3 * C_, C_);     // BIG = QKV
    attn_kernel<50, true><<<NWIN * NH, 64>>>(BIG, rel_pos, LN);  // LN = ATT
    gemm_tc<0, true, true><<<dim3(C_ / 64, MBIG / 128), 256>>>(
        LN, proj_w, proj_b, X, TMP, MBIG, C_, C_);

    // ---- Stage D: MLP ----
    ln_kernel<<<MBIG, C_>>>(TMP, n2w, n2b, LN);
    gemm_tc<1, true, false><<<dim3(HID / 64, MBIG / 128), 256>>>(
        LN, fc1_w, fc1_b, nullptr, BIG, MBIG, HID, C_);          // BIG = H1
    gemm_tc<0, true, true><<<dim3(C_ / 64, MBIG / 128), 256>>>(
        BIG, fc2_w, fc2_b, TMP, X, MBIG, C_, HID);               // X = final

    // ---- Stage E: scatter ----
    k_scatter<<<(MBIG * C_ + TPB - 1) / TPB, TPB>>>(X, out);
}